// round 1
// baseline (speedup 1.0000x reference)
#include <cuda_runtime.h>
#include <cuda_bf16.h>

// HOG: gx,gy = sobel (cross-correlation, zero pad), mag = sqrt(gx^2+gy^2),
// ang = |atan2(gx, gy)| in [0, pi], bin = floor(ang*8/pi) in 0..8,
// out[b][bin][cy][cx] = sum of mag over the 8x8 cell.
//
// Binning without atan2: ang >= k*pi/8  <=>  cot(k*pi/8)*|gx| - gy >= 0
// (valid since both vectors are in the upper half plane; sin(k*pi/8) > 0 for k=1..7).
// Predicates are monotone in k, so accumulate prefix sums A[k] and take
// per-bin = A[k] - A[k+1] once per cell. Bin 8 (ang == pi) requires gx==0 && gy<0.

__device__ __forceinline__ float fsqrt_approx(float v) {
    float r;
    asm("sqrt.approx.f32 %0, %1;" : "=f"(r) : "f"(v));
    return r;
}

__global__ void __launch_bounds__(256) hog_kernel(const float* __restrict__ x,
                                                  float* __restrict__ out) {
    const int t  = blockIdx.x * 256 + threadIdx.x;
    const int cx = t & 63;
    const int cy = (t >> 6) & 63;
    const int b  = t >> 12;
    const int C  = cx << 3;
    const int R  = cy << 3;
    const float* img = x + (size_t)b * (512 * 512);
    const bool cL = (cx > 0);
    const bool cR = (cx < 63);

    // rolling raw rows: cols C-1 .. C+8 (10 floats each)
    float rows[3][10];

#define LOAD_ROW(RI, rexpr)                                                    \
    {                                                                          \
        const int _r = (rexpr);                                                \
        if (_r >= 0 && _r < 512) {                                             \
            const float* _p = img + _r * 512 + C;                              \
            rows[RI][0] = cL ? _p[-1] : 0.f;                                   \
            float4 _v1 = *(const float4*)(_p);                                 \
            float4 _v2 = *(const float4*)(_p + 4);                             \
            rows[RI][1] = _v1.x; rows[RI][2] = _v1.y;                          \
            rows[RI][3] = _v1.z; rows[RI][4] = _v1.w;                          \
            rows[RI][5] = _v2.x; rows[RI][6] = _v2.y;                          \
            rows[RI][7] = _v2.z; rows[RI][8] = _v2.w;                          \
            rows[RI][9] = cR ? _p[8] : 0.f;                                    \
        } else {                                                               \
            _Pragma("unroll")                                                  \
            for (int _j = 0; _j < 10; _j++) rows[RI][_j] = 0.f;                \
        }                                                                      \
    }

    // Prefix accumulators: A0 = sum(mag); Ak = sum(mag | ang >= k*pi/8)
    float A0 = 0.f, A1 = 0.f, A2 = 0.f, A3 = 0.f, A4 = 0.f,
          A5 = 0.f, A6 = 0.f, A7 = 0.f, A8 = 0.f;

    LOAD_ROW(0, R - 1);
    LOAD_ROW(1, R);

#pragma unroll
    for (int rr = 0; rr < 8; rr++) {
        const int ia = rr % 3;          // row R+rr-1
        const int ib = (rr + 1) % 3;    // row R+rr
        const int ic = (rr + 2) % 3;    // row R+rr+1
        LOAD_ROW(ic, R + rr + 1);

        // vertical separable passes: s = [1,2,1] smooth, d = [-1,0,1] diff
        float s[10], d[10];
#pragma unroll
        for (int j = 0; j < 10; j++) {
            s[j] = fmaf(2.f, rows[ib][j], rows[ia][j] + rows[ic][j]);
            d[j] = rows[ic][j] - rows[ia][j];
        }

#pragma unroll
        for (int i = 0; i < 8; i++) {
            // gx = s[col+1]-s[col-1]; gy = d[col-1]+2d[col]+d[col+1]
            float gx  = s[i + 2] - s[i];
            float gy  = fmaf(2.f, d[i + 1], d[i] + d[i + 2]);
            float a   = fabsf(gx);
            float mag = fsqrt_approx(fmaf(gx, gx, gy * gy));
            float ngy = -gy;
            A0 += mag;
            // cot(k*pi/8) for k=1..7: 2.41421, 1, 0.41421, 0, -0.41421, -1, -2.41421
            if (fmaf(a,  2.414213562373095f, ngy) >= 0.f) A1 += mag;
            if (a + ngy                           >= 0.f) A2 += mag;
            if (fmaf(a,  0.4142135623730951f, ngy) >= 0.f) A3 += mag;
            if (ngy                               >= 0.f) A4 += mag;
            if (fmaf(a, -0.4142135623730951f, ngy) >= 0.f) A5 += mag;
            if (ngy - a                           >= 0.f) A6 += mag;
            if (fmaf(a, -2.414213562373095f, ngy) >= 0.f) A7 += mag;
            if (gx == 0.f && gy < 0.f)                     A8 += mag;  // ang == pi
        }
    }
#undef LOAD_ROW

    // out[b][k][cy][cx], per-bin value = A[k] - A[k+1]
    float* o = out + (size_t)b * (9 * 4096) + (cy << 6) + cx;
    o[0 * 4096] = A0 - A1;
    o[1 * 4096] = A1 - A2;
    o[2 * 4096] = A2 - A3;
    o[3 * 4096] = A3 - A4;
    o[4 * 4096] = A4 - A5;
    o[5 * 4096] = A5 - A6;
    o[6 * 4096] = A6 - A7;
    o[7 * 4096] = A7 - A8;
    o[8 * 4096] = A8;
}

extern "C" void kernel_launch(void* const* d_in, const int* in_sizes, int n_in,
                              void* d_out, int out_size) {
    const float* x = (const float*)d_in[0];
    float* out = (float*)d_out;
    // 64 batches * 64*64 cells = 262144 threads
    hog_kernel<<<1024, 256>>>(x, out);
}

// round 2
// speedup vs baseline: 1.1519x; 1.1519x over previous
#include <cuda_runtime.h>
#include <cuda_bf16.h>

// HOG: gx,gy = sobel (cross-correlation, zero pad), mag = sqrt(gx^2+gy^2),
// ang = |atan2(gx, gy)| in [0, pi], bin = floor(ang*8/pi) in 0..8,
// out[b][bin][cy][cx] = sum of mag over the 8x8 cell.
//
// Binning without atan2: ang >= k*pi/8  <=>  cot(k*pi/8)*|gx| - gy >= 0.
// Predicates monotone in k -> accumulate prefix sums A[k], per-bin = A[k]-A[k+1].
// Bin 8 (ang == pi) iff gx==0 && gy<0.
//
// R2: each 8x8 cell split across 2 adjacent lanes (4 cols x 8 rows each) to cut
// register pressure (rows[3][6] instead of rows[3][10]) and raise occupancy;
// pair combined with shfl_xor(.,1).

__device__ __forceinline__ float fsqrt_approx(float v) {
    float r;
    asm("sqrt.approx.f32 %0, %1;" : "=f"(r) : "f"(v));
    return r;
}

__global__ void __launch_bounds__(256) hog_kernel(const float* __restrict__ x,
                                                  float* __restrict__ out) {
    const int t  = blockIdx.x * 256 + threadIdx.x;
    const int h  = t & 1;            // which half of the cell (cols 0-3 / 4-7)
    const int cx = (t >> 1) & 63;
    const int cy = (t >> 7) & 63;
    const int b  = t >> 13;
    const int C  = (cx << 3) + (h << 2);   // first owned column
    const int R  = cy << 3;
    const float* img = x + (size_t)b * (512 * 512);
    const bool cL = (C > 0);
    const bool cR = (C < 508);

    // rolling raw rows: cols C-1 .. C+4 (6 floats each)
    float rows[3][6];

#define LOAD_ROW(RI, rexpr)                                                    \
    {                                                                          \
        const int _r = (rexpr);                                                \
        if ((unsigned)_r < 512u) {                                             \
            const float* _p = img + _r * 512 + C;                              \
            rows[RI][0] = cL ? _p[-1] : 0.f;                                   \
            float4 _v = *(const float4*)(_p);                                  \
            rows[RI][1] = _v.x; rows[RI][2] = _v.y;                            \
            rows[RI][3] = _v.z; rows[RI][4] = _v.w;                            \
            rows[RI][5] = cR ? _p[4] : 0.f;                                    \
        } else {                                                               \
            _Pragma("unroll")                                                  \
            for (int _j = 0; _j < 6; _j++) rows[RI][_j] = 0.f;                 \
        }                                                                      \
    }

    // Prefix accumulators: A0 = sum(mag); Ak = sum(mag | ang >= k*pi/8)
    float A0 = 0.f, A1 = 0.f, A2 = 0.f, A3 = 0.f, A4 = 0.f,
          A5 = 0.f, A6 = 0.f, A7 = 0.f, A8 = 0.f;

    LOAD_ROW(0, R - 1);
    LOAD_ROW(1, R);

#pragma unroll
    for (int rr = 0; rr < 8; rr++) {
        const int ia = rr % 3;          // row R+rr-1
        const int ib = (rr + 1) % 3;    // row R+rr
        const int ic = (rr + 2) % 3;    // row R+rr+1
        LOAD_ROW(ic, R + rr + 1);

        // vertical separable passes: s = [1,2,1] smooth, d = [-1,0,1] diff
        float s[6], d[6];
#pragma unroll
        for (int j = 0; j < 6; j++) {
            s[j] = fmaf(2.f, rows[ib][j], rows[ia][j] + rows[ic][j]);
            d[j] = rows[ic][j] - rows[ia][j];
        }

#pragma unroll
        for (int i = 0; i < 4; i++) {
            // gx = s[col+1]-s[col-1]; gy = d[col-1]+2d[col]+d[col+1]
            float gx  = s[i + 2] - s[i];
            float gy  = fmaf(2.f, d[i + 1], d[i] + d[i + 2]);
            float a   = fabsf(gx);
            float mag = fsqrt_approx(fmaf(gx, gx, gy * gy));
            A0 += mag;
            // cot(k*pi/8) for k=1..7: 2.41421, 1, 0.41421, 0, -0.41421, -1, -2.41421
            if (fmaf(a,  2.414213562373095f, -gy) >= 0.f)  A1 += mag;
            if (a - gy                            >= 0.f)  A2 += mag;
            if (fmaf(a,  0.4142135623730951f, -gy) >= 0.f) A3 += mag;
            if (gy                                <= 0.f)  A4 += mag;
            if (fmaf(a, -0.4142135623730951f, -gy) >= 0.f) A5 += mag;
            if (a + gy                            <= 0.f)  A6 += mag;
            if (fmaf(a, -2.414213562373095f, -gy) >= 0.f)  A7 += mag;
            if (gx == 0.f && gy < 0.f)                     A8 += mag;  // ang == pi
        }
    }
#undef LOAD_ROW

    // combine the two half-cell lanes (partner differs in lane bit 0)
    A0 += __shfl_xor_sync(0xFFFFFFFFu, A0, 1);
    A1 += __shfl_xor_sync(0xFFFFFFFFu, A1, 1);
    A2 += __shfl_xor_sync(0xFFFFFFFFu, A2, 1);
    A3 += __shfl_xor_sync(0xFFFFFFFFu, A3, 1);
    A4 += __shfl_xor_sync(0xFFFFFFFFu, A4, 1);
    A5 += __shfl_xor_sync(0xFFFFFFFFu, A5, 1);
    A6 += __shfl_xor_sync(0xFFFFFFFFu, A6, 1);
    A7 += __shfl_xor_sync(0xFFFFFFFFu, A7, 1);
    A8 += __shfl_xor_sync(0xFFFFFFFFu, A8, 1);

    // out[b][k][cy][cx], per-bin value = A[k] - A[k+1]; split writes across pair
    float* o = out + (size_t)b * (9 * 4096) + (cy << 6) + cx;
    if (h == 0) {
        o[0 * 4096] = A0 - A1;
        o[1 * 4096] = A1 - A2;
        o[2 * 4096] = A2 - A3;
        o[3 * 4096] = A3 - A4;
        o[4 * 4096] = A4 - A5;
    } else {
        o[5 * 4096] = A5 - A6;
        o[6 * 4096] = A6 - A7;
        o[7 * 4096] = A7 - A8;
        o[8 * 4096] = A8;
    }
}

extern "C" void kernel_launch(void* const* d_in, const int* in_sizes, int n_in,
                              void* d_out, int out_size) {
    const float* x = (const float*)d_in[0];
    float* out = (float*)d_out;
    // 64 batches * 64*64 cells * 2 half-cells = 524288 threads
    hog_kernel<<<2048, 256>>>(x, out);
}